// round 5
// baseline (speedup 1.0000x reference)
#include <cuda_runtime.h>
#include <cstdint>
#include <cstddef>

// Problem constants
#define BB   256     // batch
#define SS   512     // seq len
#define VV   50000   // vocab
#define EE   300     // embed dim
#define HH   128     // hidden
#define NG   1024    // 2 dirs * 4H gate columns

// ---------------------------------------------------------------------------
// Scratch (static device globals — no runtime allocation allowed)
// ---------------------------------------------------------------------------
__device__ __align__(16) float g_P  [(size_t)VV * NG];        // projected vocab table (+b0 folded)
__device__ __align__(16) float g_h0 [(size_t)SS * BB * 256];  // layer-0 output [s*B+b][2H]
__device__ __align__(16) float g_gx1[(size_t)SS * BB * NG];   // layer-1 input projections (+b1 folded)
__device__ __align__(16) float g_hT [(size_t)BB * 256];       // layer-1 final hidden [b][2H]

// ---------------------------------------------------------------------------
// Packed fp32x2 helpers — clean u64 dataflow (no aliasing UB; asm outputs are
// genuinely consumed so the non-volatile asm cannot be dead-coded).
// ---------------------------------------------------------------------------
__device__ __forceinline__ void ffma2(unsigned long long& c,
                                      unsigned long long a,
                                      unsigned long long b) {
    asm("fma.rn.f32x2 %0, %1, %2, %0;" : "+l"(c) : "l"(a), "l"(b));
}
__device__ __forceinline__ unsigned long long bcast2(float x) {
    unsigned long long r;
    asm("mov.b64 %0, {%1, %1};" : "=l"(r) : "f"(x));
    return r;
}
__device__ __forceinline__ float2 unpk2(unsigned long long v) {
    float2 f;
    asm("mov.b64 {%0, %1}, %2;" : "=f"(f.x), "=f"(f.y) : "l"(v));
    return f;
}

__device__ __forceinline__ float sigm_f(float x) {
    return 1.0f / (1.0f + __expf(-x));
}
__device__ __forceinline__ float tanh_f(float x) {
    float a = fabsf(x);
    float t = __expf(-2.0f * a);
    float r = (1.0f - t) / (1.0f + t);
    return copysignf(r, x);
}

// ---------------------------------------------------------------------------
// GEMM: C[M,1024] = A[M,K] @ Bw[1024,K]^T + bias[1024]
// BM=128, BN=128, BK=16, 256 threads, 8x8 per-thread microtile, f32x2 packed
// along M pairs. WHICH==0: A=Aarg, C=g_P.  WHICH==1: A=g_h0, C=g_gx1.
// ---------------------------------------------------------------------------
template<int WHICH>
__global__ __launch_bounds__(256, 2)
void gemm_bias_kernel(const float* __restrict__ Aarg,
                      const float* __restrict__ Bw,
                      const float* __restrict__ bias,
                      int M, int K)
{
    const float* __restrict__ A = (WHICH == 0) ? Aarg : g_h0;
    float* __restrict__ C       = (WHICH == 0) ? g_P  : g_gx1;

    __shared__ __align__(16) float As[16][128];
    __shared__ __align__(16) float Bs[16][128];

    const int tid   = threadIdx.x;
    const int mTile = blockIdx.y * 128;
    const int nTile = blockIdx.x * 128;
    const int n_base = (tid & 15) * 8;
    const int m_base = (tid >> 4) * 8;

    unsigned long long acc[4][8];
    #pragma unroll
    for (int i = 0; i < 4; i++)
        #pragma unroll
        for (int j = 0; j < 8; j++) acc[i][j] = 0ull;

    const int lr = tid >> 2;          // 0..63
    const int lk = (tid & 3) * 4;     // 0,4,8,12

    const int nKT = (K + 15) >> 4;
    for (int kt = 0; kt < nKT; kt++) {
        const int k0 = kt << 4;
        // ---- load A tile (transposed into smem); K % 4 == 0 for both cases
        #pragma unroll
        for (int i = 0; i < 2; i++) {
            int row = lr + i * 64;
            int gm  = mTile + row;
            int gk  = k0 + lk;
            float4 v = make_float4(0.f, 0.f, 0.f, 0.f);
            if (gm < M && gk < K)
                v = *reinterpret_cast<const float4*>(&A[(size_t)gm * K + gk]);
            As[lk + 0][row] = v.x; As[lk + 1][row] = v.y;
            As[lk + 2][row] = v.z; As[lk + 3][row] = v.w;
        }
        // ---- load B tile (N rows always valid: N==1024)
        #pragma unroll
        for (int i = 0; i < 2; i++) {
            int row = lr + i * 64;
            int gn  = nTile + row;
            int gk  = k0 + lk;
            float4 v = make_float4(0.f, 0.f, 0.f, 0.f);
            if (gk < K)
                v = *reinterpret_cast<const float4*>(&Bw[(size_t)gn * K + gk]);
            Bs[lk + 0][row] = v.x; Bs[lk + 1][row] = v.y;
            Bs[lk + 2][row] = v.z; Bs[lk + 3][row] = v.w;
        }
        __syncthreads();

        #pragma unroll
        for (int k = 0; k < 16; k++) {
            ulonglong2 a01 = *reinterpret_cast<const ulonglong2*>(&As[k][m_base]);
            ulonglong2 a23 = *reinterpret_cast<const ulonglong2*>(&As[k][m_base + 4]);
            float4 b0 = *reinterpret_cast<const float4*>(&Bs[k][n_base]);
            float4 b1 = *reinterpret_cast<const float4*>(&Bs[k][n_base + 4]);
            unsigned long long bbk[8] = {
                bcast2(b0.x), bcast2(b0.y), bcast2(b0.z), bcast2(b0.w),
                bcast2(b1.x), bcast2(b1.y), bcast2(b1.z), bcast2(b1.w)
            };
            #pragma unroll
            for (int j = 0; j < 8; j++) {
                ffma2(acc[0][j], a01.x, bbk[j]);
                ffma2(acc[1][j], a01.y, bbk[j]);
                ffma2(acc[2][j], a23.x, bbk[j]);
                ffma2(acc[3][j], a23.y, bbk[j]);
            }
        }
        __syncthreads();
    }

    // ---- epilogue: unpack, add bias, vectorized stores
    const int gn = nTile + n_base;
    float bv[8];
    #pragma unroll
    for (int j = 0; j < 8; j++) bv[j] = bias[gn + j];

    #pragma unroll
    for (int i = 0; i < 4; i++) {
        int gm0 = mTile + m_base + 2 * i;
        float2 u[8];
        #pragma unroll
        for (int j = 0; j < 8; j++) u[j] = unpk2(acc[i][j]);
        float4 lo0 = make_float4(u[0].x + bv[0], u[1].x + bv[1], u[2].x + bv[2], u[3].x + bv[3]);
        float4 lo1 = make_float4(u[4].x + bv[4], u[5].x + bv[5], u[6].x + bv[6], u[7].x + bv[7]);
        float4 hi0 = make_float4(u[0].y + bv[0], u[1].y + bv[1], u[2].y + bv[2], u[3].y + bv[3]);
        float4 hi1 = make_float4(u[4].y + bv[4], u[5].y + bv[5], u[6].y + bv[6], u[7].y + bv[7]);
        if (gm0 < M) {
            *reinterpret_cast<float4*>(&C[(size_t)gm0 * NG + gn])     = lo0;
            *reinterpret_cast<float4*>(&C[(size_t)gm0 * NG + gn + 4]) = lo1;
        }
        if (gm0 + 1 < M) {
            *reinterpret_cast<float4*>(&C[(size_t)(gm0 + 1) * NG + gn])     = hi0;
            *reinterpret_cast<float4*>(&C[(size_t)(gm0 + 1) * NG + gn + 4]) = hi1;
        }
    }
}

// ---------------------------------------------------------------------------
// Recurrence kernel. One block = 4 batch rows x one direction x one layer.
// 512 threads. Thread t owns FULL gate row g=t (all 512 rows covered — this
// fixes the round-2 half-coverage bug): z[g,b] = gx[g,b] + w_hh[g,:] . h[b,:].
// w row split: k in [0,64) lives in registers as 32 k-pair-packed u64;
// k in [64,128) lives in smem (pitch 68 floats -> conflict-free LDS.128).
// Accumulation is f32x2 over k-pairs (lane0=even-k, lane1=odd-k partials),
// one cross-lane add at the end. h broadcast-read from smem as ulonglong2.
// Every thread is also a combiner for cell (bb=t>>7, jj=t&127), keeping c in
// a register.
// LAYER==0: gx gathered from g_P via tokens; writes h seq to g_h0 each step.
// LAYER==1: gx = g_gx1; writes final hidden to g_hT after the loop.
// Dynamic smem layout (bytes):
//   [0, 139264)            w_sm  512 rows x 68-float pitch (k 64..127 in cols 0..63)
//   [139264, 141312)       h_sm  [4][128] floats
//   [141312, 151552)       z_sm  [512][5] floats (pitch 5 -> conflict-free)
//   [151552, 159744)       tok_sm [4][512] int
// ---------------------------------------------------------------------------
#define REC_SMEM_BYTES 159744

template<int LAYER>
__global__ __launch_bounds__(512, 1)
void recur_kernel(const int* __restrict__ tokens,
                  const float* __restrict__ w_hh)   // [2,512,128]
{
    extern __shared__ __align__(16) float smem[];
    float* w_sm   = smem;                   // 512*68 floats
    float* h_sm   = smem + 512 * 68;        // 512 floats
    float* z_sm   = h_sm + 512;             // 2560 floats
    int*   tok_sm = (int*)(z_sm + 2560);    // 2048 ints

    const int tid   = threadIdx.x;
    const int chunk = blockIdx.x;   // 64 chunks of 4 batch rows
    const int dir   = blockIdx.y;   // 0 fwd, 1 bwd
    const int g     = tid;          // gate row 0..511

    // ---- w_hh row g, k 0..63 into registers as 32 packed k-pairs
    unsigned long long wr2[32];
    {
        const unsigned long long* wp = reinterpret_cast<const unsigned long long*>(
            &w_hh[((size_t)dir * 512 + g) * 128]);
        #pragma unroll
        for (int i = 0; i < 32; i++) wr2[i] = wp[i];
    }
    // ---- w_hh k 64..127 into smem (coalesced 64-float runs per row)
    for (int idx = tid; idx < 512 * 64; idx += 512) {
        int gg = idx >> 6, kk = idx & 63;
        w_sm[gg * 68 + kk] = w_hh[((size_t)dir * 512 + gg) * 128 + 64 + kk];
    }
    if (LAYER == 0) {
        for (int idx = tid; idx < 4 * 512; idx += 512)
            tok_sm[idx] = tokens[(size_t)(chunk * 4 + (idx >> 9)) * SS + (idx & 511)];
    }
    h_sm[tid] = 0.0f;   // 512 entries, one per thread
    __syncthreads();

    const int jj = tid & 127;   // hidden unit of this combiner thread
    const int bb = tid >> 7;    // batch row (0..3) of this combiner thread
    const int col = dir * 512 + g;
    const float* __restrict__ gsrc = (LAYER == 0) ? g_P : g_gx1;
    float c_st = 0.0f, h_last = 0.0f;

    for (int si = 0; si < 512; si++) {
        const int s = dir ? (511 - si) : si;

        // --- input projections (issued early; latency hidden behind FMAs)
        float gxv[4];
        #pragma unroll
        for (int b = 0; b < 4; b++) {
            size_t row = (LAYER == 0)
                ? (size_t)tok_sm[b * 512 + s]
                : ((size_t)s * BB + (chunk * 4 + b));
            gxv[b] = gsrc[row * NG + col];
        }

        // --- full-k dot for this gate row, 4 batch cols, f32x2 over k-pairs
        unsigned long long acc[4] = {0ull, 0ull, 0ull, 0ull};
        #pragma unroll
        for (int t = 0; t < 16; t++) {          // register half: k = 4t..4t+3
            #pragma unroll
            for (int b = 0; b < 4; b++) {
                ulonglong2 h2 = *reinterpret_cast<const ulonglong2*>(&h_sm[b * 128 + t * 4]);
                ffma2(acc[b], wr2[2 * t],     h2.x);
                ffma2(acc[b], wr2[2 * t + 1], h2.y);
            }
        }
        const float* wrow = &w_sm[g * 68];
        #pragma unroll
        for (int t = 0; t < 16; t++) {          // smem half: k = 64 + 4t..
            ulonglong2 w2 = *reinterpret_cast<const ulonglong2*>(&wrow[t * 4]);
            #pragma unroll
            for (int b = 0; b < 4; b++) {
                ulonglong2 h2 = *reinterpret_cast<const ulonglong2*>(&h_sm[b * 128 + 64 + t * 4]);
                ffma2(acc[b], w2.x, h2.x);
                ffma2(acc[b], w2.y, h2.y);
            }
        }
        #pragma unroll
        for (int b = 0; b < 4; b++) {
            float2 f = unpk2(acc[b]);
            z_sm[g * 5 + b] = f.x + f.y + gxv[b];
        }
        __syncthreads();

        // --- gate combine (torch order i,f,g,o) for cell (bb, jj)
        {
            float zi = z_sm[(      jj) * 5 + bb];
            float zf = z_sm[(128 + jj) * 5 + bb];
            float zg = z_sm[(256 + jj) * 5 + bb];
            float zo = z_sm[(384 + jj) * 5 + bb];
            float ig = sigm_f(zi), fg = sigm_f(zf), og = sigm_f(zo);
            float gv = tanh_f(zg);
            c_st = fg * c_st + ig * gv;
            float hh = og * tanh_f(c_st);
            h_last = hh;
            h_sm[bb * 128 + jj] = hh;
            if (LAYER == 0)
                g_h0[((size_t)s * BB + (chunk * 4 + bb)) * 256 + dir * 128 + jj] = hh;
        }
        __syncthreads();
    }

    if (LAYER == 1)
        g_hT[(size_t)(chunk * 4 + bb) * 256 + dir * 128 + jj] = h_last;
}

// ---------------------------------------------------------------------------
// FC head: out[b] = relu(hT[b] @ fc1_w^T + fc1_b) @ fc2_w^T + fc2_b
// One block (128 threads) per batch row. Negligible runtime.
// ---------------------------------------------------------------------------
__global__ __launch_bounds__(128)
void fc_kernel(const float* __restrict__ fc1w, const float* __restrict__ fc1b,
               const float* __restrict__ fc2w, const float* __restrict__ fc2b,
               float* __restrict__ out)
{
    __shared__ float xs[256];
    __shared__ float red[4];
    const int b = blockIdx.x, tid = threadIdx.x;
    xs[tid]       = g_hT[(size_t)b * 256 + tid];
    xs[tid + 128] = g_hT[(size_t)b * 256 + 128 + tid];
    __syncthreads();

    float s = fc1b[tid];
    const float* wr = &fc1w[(size_t)tid * 256];
    #pragma unroll 8
    for (int k = 0; k < 256; k++) s += xs[k] * wr[k];
    float a = fmaxf(s, 0.0f);

    for (int o = 0; o < 2; o++) {
        float v = a * fc2w[o * 128 + tid];
        #pragma unroll
        for (int off = 16; off > 0; off >>= 1)
            v += __shfl_xor_sync(0xffffffffu, v, off);
        if ((tid & 31) == 0) red[tid >> 5] = v;
        __syncthreads();
        if (tid == 0)
            out[b * 2 + o] = red[0] + red[1] + red[2] + red[3] + fc2b[o];
        __syncthreads();
    }
}

// ---------------------------------------------------------------------------
// Launcher (graph-capturable: kernel launches only, default stream)
// ---------------------------------------------------------------------------
extern "C" void kernel_launch(void* const* d_in, const int* in_sizes, int n_in,
                              void* d_out, int out_size)
{
    const int*   tokens = (const int*)  d_in[0];   // [B,S]
    const float* emb    = (const float*)d_in[1];   // [V,E]
    const float* w_ih0  = (const float*)d_in[2];   // [2,4H,E]  -> flat [1024,300]
    const float* w_hh0  = (const float*)d_in[3];   // [2,4H,H]
    const float* b0     = (const float*)d_in[4];   // [2,4H]    -> flat [1024]
    const float* w_ih1  = (const float*)d_in[5];   // [2,4H,2H] -> flat [1024,256]
    const float* w_hh1  = (const float*)d_in[6];   // [2,4H,H]
    const float* b1     = (const float*)d_in[7];   // [2,4H]
    const float* fc1w   = (const float*)d_in[8];   // [H,2H]
    const float* fc1b   = (const float*)d_in[9];   // [H]
    const float* fc2w   = (const float*)d_in[10];  // [2,H]
    const float* fc2b   = (const float*)d_in[11];  // [2]
    float* out = (float*)d_out;

    static int configured = 0;
    if (!configured) {
        cudaFuncSetAttribute((const void*)recur_kernel<0>,
                             cudaFuncAttributeMaxDynamicSharedMemorySize, REC_SMEM_BYTES);
        cudaFuncSetAttribute((const void*)recur_kernel<1>,
                             cudaFuncAttributeMaxDynamicSharedMemorySize, REC_SMEM_BYTES);
        configured = 1;
    }

    // 1) Projected vocab table: P = emb @ w_ih0^T + b0   [50000,1024]
    {
        dim3 grid(NG / 128, (VV + 127) / 128);   // (8, 391)
        gemm_bias_kernel<0><<<grid, 256>>>(emb, w_ih0, b0, VV, EE);
    }
    // 2) Layer-0 bidirectional recurrence (gx gathered from P)
    {
        dim3 grid(64, 2);
        recur_kernel<0><<<grid, 512, REC_SMEM_BYTES>>>(tokens, w_hh0);
    }
    // 3) Layer-1 input projections: gx1 = h0_seq @ w_ih1^T + b1  [131072,1024]
    {
        dim3 grid(NG / 128, (SS * BB) / 128);    // (8, 1024)
        gemm_bias_kernel<1><<<grid, 256>>>(nullptr, w_ih1, b1, SS * BB, 256);
    }
    // 4) Layer-1 bidirectional recurrence -> final hidden states
    {
        dim3 grid(64, 2);
        recur_kernel<1><<<grid, 512, REC_SMEM_BYTES>>>(tokens, w_hh1);
    }
    // 5) MLP head
    fc_kernel<<<BB, 128>>>(fc1w, fc1b, fc2w, fc2b, out);
}

// round 6
// speedup vs baseline: 1.0078x; 1.0078x over previous
#include <cuda_runtime.h>
#include <cstdint>
#include <cstddef>

// Problem constants
#define BB   256     // batch
#define SS   512     // seq len
#define VV   50000   // vocab
#define EE   300     // embed dim
#define HH   128     // hidden
#define NG   1024    // 2 dirs * 4H gate columns

// ---------------------------------------------------------------------------
// Scratch (static device globals — no runtime allocation allowed)
// ---------------------------------------------------------------------------
__device__ __align__(16) float g_P  [(size_t)VV * NG];        // projected vocab table (+b0 folded)
__device__ __align__(16) float g_h0 [(size_t)SS * BB * 256];  // layer-0 output [s*B+b][2H]
__device__ __align__(16) float g_gx1[(size_t)SS * BB * NG];   // layer-1 input projections (+b1 folded)
__device__ __align__(16) float g_hT [(size_t)BB * 256];       // layer-1 final hidden [b][2H]

// ---------------------------------------------------------------------------
// Packed fp32x2 helpers — clean u64 dataflow (no aliasing UB)
// ---------------------------------------------------------------------------
__device__ __forceinline__ void ffma2(unsigned long long& c,
                                      unsigned long long a,
                                      unsigned long long b) {
    asm("fma.rn.f32x2 %0, %1, %2, %0;" : "+l"(c) : "l"(a), "l"(b));
}
__device__ __forceinline__ unsigned long long bcast2(float x) {
    unsigned long long r;
    asm("mov.b64 %0, {%1, %1};" : "=l"(r) : "f"(x));
    return r;
}
__device__ __forceinline__ float2 unpk2(unsigned long long v) {
    float2 f;
    asm("mov.b64 {%0, %1}, %2;" : "=f"(f.x), "=f"(f.y) : "l"(v));
    return f;
}

__device__ __forceinline__ float sigm_f(float x) {
    return 1.0f / (1.0f + __expf(-x));
}
__device__ __forceinline__ float tanh_f(float x) {
    float a = fabsf(x);
    float t = __expf(-2.0f * a);
    float r = (1.0f - t) / (1.0f + t);
    return copysignf(r, x);
}

// ---------------------------------------------------------------------------
// GEMM: C[M,1024] = A[M,K] @ Bw[1024,K]^T + bias[1024]
// BM=128, BN=128, BK=16, 256 threads, 8x8 per-thread microtile, f32x2 packed
// along M pairs. Ping-pong double-buffered smem: ONE __syncthreads per k-tile,
// next tile's global loads issued before compute (latency overlapped).
// WHICH==0: A=Aarg, C=g_P.  WHICH==1: A=g_h0, C=g_gx1.
// ---------------------------------------------------------------------------
template<int WHICH>
__global__ __launch_bounds__(256, 2)
void gemm_bias_kernel(const float* __restrict__ Aarg,
                      const float* __restrict__ Bw,
                      const float* __restrict__ bias,
                      int M, int K)
{
    const float* __restrict__ A = (WHICH == 0) ? Aarg : g_h0;
    float* __restrict__ C       = (WHICH == 0) ? g_P  : g_gx1;

    __shared__ __align__(16) float As[2][16][128];
    __shared__ __align__(16) float Bs[2][16][128];

    const int tid   = threadIdx.x;
    const int mTile = blockIdx.y * 128;
    const int nTile = blockIdx.x * 128;
    const int n_base = (tid & 15) * 8;
    const int m_base = (tid >> 4) * 8;

    unsigned long long acc[4][8];
    #pragma unroll
    for (int i = 0; i < 4; i++)
        #pragma unroll
        for (int j = 0; j < 8; j++) acc[i][j] = 0ull;

    const int lr = tid >> 2;          // 0..63
    const int lk = (tid & 3) * 4;     // 0,4,8,12
    const int nKT = (K + 15) >> 4;

    // ---- load tile 0 into buffer 0
    {
        #pragma unroll
        for (int i = 0; i < 2; i++) {
            int row = lr + i * 64;
            int gm  = mTile + row;
            float4 v = make_float4(0.f, 0.f, 0.f, 0.f);
            if (gm < M && lk < K)
                v = *reinterpret_cast<const float4*>(&A[(size_t)gm * K + lk]);
            As[0][lk + 0][row] = v.x; As[0][lk + 1][row] = v.y;
            As[0][lk + 2][row] = v.z; As[0][lk + 3][row] = v.w;
            int gn = nTile + row;
            float4 w = make_float4(0.f, 0.f, 0.f, 0.f);
            if (lk < K)
                w = *reinterpret_cast<const float4*>(&Bw[(size_t)gn * K + lk]);
            Bs[0][lk + 0][row] = w.x; Bs[0][lk + 1][row] = w.y;
            Bs[0][lk + 2][row] = w.z; Bs[0][lk + 3][row] = w.w;
        }
    }
    __syncthreads();

    for (int kt = 0; kt < nKT; kt++) {
        const int cur = kt & 1;
        const int nxt = cur ^ 1;

        // ---- prefetch next tile into registers (overlaps with compute below)
        float4 pa[2], pb[2];
        const bool havenext = (kt + 1 < nKT);
        if (havenext) {
            const int k0 = (kt + 1) << 4;
            #pragma unroll
            for (int i = 0; i < 2; i++) {
                int row = lr + i * 64;
                int gm  = mTile + row;
                int gk  = k0 + lk;
                pa[i] = make_float4(0.f, 0.f, 0.f, 0.f);
                if (gm < M && gk < K)
                    pa[i] = *reinterpret_cast<const float4*>(&A[(size_t)gm * K + gk]);
                int gn = nTile + row;
                pb[i] = make_float4(0.f, 0.f, 0.f, 0.f);
                if (gk < K)
                    pb[i] = *reinterpret_cast<const float4*>(&Bw[(size_t)gn * K + gk]);
            }
        }

        // ---- compute on current buffer
        #pragma unroll
        for (int k = 0; k < 16; k++) {
            ulonglong2 a01 = *reinterpret_cast<const ulonglong2*>(&As[cur][k][m_base]);
            ulonglong2 a23 = *reinterpret_cast<const ulonglong2*>(&As[cur][k][m_base + 4]);
            float4 b0 = *reinterpret_cast<const float4*>(&Bs[cur][k][n_base]);
            float4 b1 = *reinterpret_cast<const float4*>(&Bs[cur][k][n_base + 4]);
            unsigned long long bbk[8] = {
                bcast2(b0.x), bcast2(b0.y), bcast2(b0.z), bcast2(b0.w),
                bcast2(b1.x), bcast2(b1.y), bcast2(b1.z), bcast2(b1.w)
            };
            #pragma unroll
            for (int j = 0; j < 8; j++) {
                ffma2(acc[0][j], a01.x, bbk[j]);
                ffma2(acc[1][j], a01.y, bbk[j]);
                ffma2(acc[2][j], a23.x, bbk[j]);
                ffma2(acc[3][j], a23.y, bbk[j]);
            }
        }

        // ---- store prefetched tile into the other buffer, one sync per iter
        if (havenext) {
            #pragma unroll
            for (int i = 0; i < 2; i++) {
                int row = lr + i * 64;
                As[nxt][lk + 0][row] = pa[i].x; As[nxt][lk + 1][row] = pa[i].y;
                As[nxt][lk + 2][row] = pa[i].z; As[nxt][lk + 3][row] = pa[i].w;
                Bs[nxt][lk + 0][row] = pb[i].x; Bs[nxt][lk + 1][row] = pb[i].y;
                Bs[nxt][lk + 2][row] = pb[i].z; Bs[nxt][lk + 3][row] = pb[i].w;
            }
        }
        __syncthreads();
    }

    // ---- epilogue: unpack, add bias, vectorized stores
    const int gn = nTile + n_base;
    float bv[8];
    #pragma unroll
    for (int j = 0; j < 8; j++) bv[j] = bias[gn + j];

    #pragma unroll
    for (int i = 0; i < 4; i++) {
        int gm0 = mTile + m_base + 2 * i;
        float2 u[8];
        #pragma unroll
        for (int j = 0; j < 8; j++) u[j] = unpk2(acc[i][j]);
        float4 lo0 = make_float4(u[0].x + bv[0], u[1].x + bv[1], u[2].x + bv[2], u[3].x + bv[3]);
        float4 lo1 = make_float4(u[4].x + bv[4], u[5].x + bv[5], u[6].x + bv[6], u[7].x + bv[7]);
        float4 hi0 = make_float4(u[0].y + bv[0], u[1].y + bv[1], u[2].y + bv[2], u[3].y + bv[3]);
        float4 hi1 = make_float4(u[4].y + bv[4], u[5].y + bv[5], u[6].y + bv[6], u[7].y + bv[7]);
        if (gm0 < M) {
            *reinterpret_cast<float4*>(&C[(size_t)gm0 * NG + gn])     = lo0;
            *reinterpret_cast<float4*>(&C[(size_t)gm0 * NG + gn + 4]) = lo1;
        }
        if (gm0 + 1 < M) {
            *reinterpret_cast<float4*>(&C[(size_t)(gm0 + 1) * NG + gn])     = hi0;
            *reinterpret_cast<float4*>(&C[(size_t)(gm0 + 1) * NG + gn + 4]) = hi1;
        }
    }
}

// ---------------------------------------------------------------------------
// Recurrence kernel. One block = 4 batch rows x one direction x one layer.
// 512 threads; thread t owns full gate row g=t:
//   z[g,b] = gx[g,b] + w_hh[g,:] . h[b,:]
// w row split: k in [0,64) in registers (32 k-pair u64); k in [64,128) in
// smem QUAD-TRANSPOSED as w_sm4[t][g][4] so a warp's LDS.128 are consecutive
// 16B addresses -> ZERO bank conflicts (round-5 fix: pitch-68 layout was
// 4-way conflicted and made the kernel L1-bound at 72%).
// f32x2 accumulation over k-pairs; h broadcast-read as ulonglong2.
// Every thread also combines cell (bb=t>>7, jj=t&127), c kept in a register.
// LAYER==0: gx gathered from g_P via tokens; writes h seq to g_h0 each step.
// LAYER==1: gx = g_gx1; writes final hidden to g_hT after the loop.
// Dynamic smem (floats): w_sm4 16*512*4 =32768 | h_sm 512 | z_sm 2560 | tok 2048i
// ---------------------------------------------------------------------------
#define REC_SMEM_BYTES ((32768 + 512 + 2560) * 4 + 2048 * 4)

template<int LAYER>
__global__ __launch_bounds__(512, 1)
void recur_kernel(const int* __restrict__ tokens,
                  const float* __restrict__ w_hh)   // [2,512,128]
{
    extern __shared__ __align__(16) float smem[];
    float* w_sm4  = smem;                    // [16][512][4] floats
    float* h_sm   = smem + 32768;            // [4][128]
    float* z_sm   = h_sm + 512;              // [512][5]
    int*   tok_sm = (int*)(z_sm + 2560);     // [4][512]

    const int tid   = threadIdx.x;
    const int chunk = blockIdx.x;   // 64 chunks of 4 batch rows
    const int dir   = blockIdx.y;   // 0 fwd, 1 bwd
    const int g     = tid;          // gate row 0..511

    // ---- w_hh row g, k 0..63 into registers as 32 packed k-pairs
    unsigned long long wr2[32];
    {
        const unsigned long long* wp = reinterpret_cast<const unsigned long long*>(
            &w_hh[((size_t)dir * 512 + g) * 128]);
        #pragma unroll
        for (int i = 0; i < 32; i++) wr2[i] = wp[i];
    }
    // ---- w_hh k 64..127 into smem, quad-transposed: w_sm4[(kk>>2)][gg][kk&3]
    for (int idx = tid; idx < 512 * 64; idx += 512) {
        int gg = idx >> 6, kk = idx & 63;
        w_sm4[(kk >> 2) * 2048 + gg * 4 + (kk & 3)] =
            w_hh[((size_t)dir * 512 + gg) * 128 + 64 + kk];
    }
    if (LAYER == 0) {
        for (int idx = tid; idx < 4 * 512; idx += 512)
            tok_sm[idx] = tokens[(size_t)(chunk * 4 + (idx >> 9)) * SS + (idx & 511)];
    }
    h_sm[tid] = 0.0f;
    __syncthreads();

    const int jj = tid & 127;   // hidden unit of this combiner thread
    const int bb = tid >> 7;    // batch row (0..3) of this combiner thread
    const int col = dir * 512 + g;
    const float* __restrict__ gsrc = (LAYER == 0) ? g_P : g_gx1;
    float c_st = 0.0f, h_last = 0.0f;

    for (int si = 0; si < 512; si++) {
        const int s = dir ? (511 - si) : si;

        // --- input projections (issued early; latency hidden behind FMAs)
        float gxv[4];
        #pragma unroll
        for (int b = 0; b < 4; b++) {
            size_t row = (LAYER == 0)
                ? (size_t)tok_sm[b * 512 + s]
                : ((size_t)s * BB + (chunk * 4 + b));
            gxv[b] = gsrc[row * NG + col];
        }

        // --- full-k dot for this gate row, 4 batch cols, f32x2 over k-pairs
        unsigned long long acc[4] = {0ull, 0ull, 0ull, 0ull};
        #pragma unroll
        for (int t = 0; t < 16; t++) {          // register half: k = 4t..4t+3
            #pragma unroll
            for (int b = 0; b < 4; b++) {
                ulonglong2 h2 = *reinterpret_cast<const ulonglong2*>(&h_sm[b * 128 + t * 4]);
                ffma2(acc[b], wr2[2 * t],     h2.x);
                ffma2(acc[b], wr2[2 * t + 1], h2.y);
            }
        }
        #pragma unroll
        for (int t = 0; t < 16; t++) {          // smem half: k = 64+4t..64+4t+3
            ulonglong2 w2 = *reinterpret_cast<const ulonglong2*>(&w_sm4[t * 2048 + g * 4]);
            #pragma unroll
            for (int b = 0; b < 4; b++) {
                ulonglong2 h2 = *reinterpret_cast<const ulonglong2*>(&h_sm[b * 128 + 64 + t * 4]);
                ffma2(acc[b], w2.x, h2.x);
                ffma2(acc[b], w2.y, h2.y);
            }
        }
        #pragma unroll
        for (int b = 0; b < 4; b++) {
            float2 f = unpk2(acc[b]);
            z_sm[g * 5 + b] = f.x + f.y + gxv[b];
        }
        __syncthreads();

        // --- gate combine (torch order i,f,g,o) for cell (bb, jj)
        {
            float zi = z_sm[(      jj) * 5 + bb];
            float zf = z_sm[(128 + jj) * 5 + bb];
            float zg = z_sm[(256 + jj) * 5 + bb];
            float zo = z_sm[(384 + jj) * 5 + bb];
            float ig = sigm_f(zi), fg = sigm_f(zf), og = sigm_f(zo);
            float gv = tanh_f(zg);
            c_st = fg * c_st + ig * gv;
            float hh = og * tanh_f(c_st);
            h_last = hh;
            h_sm[bb * 128 + jj] = hh;
            if (LAYER == 0)
                g_h0[((size_t)s * BB + (chunk * 4 + bb)) * 256 + dir * 128 + jj] = hh;
        }
        __syncthreads();
    }

    if (LAYER == 1)
        g_hT[(size_t)(chunk * 4 + bb) * 256 + dir * 128 + jj] = h_last;
}

// ---------------------------------------------------------------------------
// FC head: out[b] = relu(hT[b] @ fc1_w^T + fc1_b) @ fc2_w^T + fc2_b
// ---------------------------------------------------------------------------
__global__ __launch_bounds__(128)
void fc_kernel(const float* __restrict__ fc1w, const float* __restrict__ fc1b,
               const float* __restrict__ fc2w, const float* __restrict__ fc2b,
               float* __restrict__ out)
{
    __shared__ float xs[256];
    __shared__ float red[4];
    const int b = blockIdx.x, tid = threadIdx.x;
    xs[tid]       = g_hT[(size_t)b * 256 + tid];
    xs[tid + 128] = g_hT[(size_t)b * 256 + 128 + tid];
    __syncthreads();

    float s = fc1b[tid];
    const float* wr = &fc1w[(size_t)tid * 256];
    #pragma unroll 8
    for (int k = 0; k < 256; k++) s += xs[k] * wr[k];
    float a = fmaxf(s, 0.0f);

    for (int o = 0; o < 2; o++) {
        float v = a * fc2w[o * 128 + tid];
        #pragma unroll
        for (int off = 16; off > 0; off >>= 1)
            v += __shfl_xor_sync(0xffffffffu, v, off);
        if ((tid & 31) == 0) red[tid >> 5] = v;
        __syncthreads();
        if (tid == 0)
            out[b * 2 + o] = red[0] + red[1] + red[2] + red[3] + fc2b[o];
        __syncthreads();
    }
}

// ---------------------------------------------------------------------------
// Launcher (graph-capturable: kernel launches only, default stream)
// ---------------------------------------------------------------------------
extern "C" void kernel_launch(void* const* d_in, const int* in_sizes, int n_in,
                              void* d_out, int out_size)
{
    const int*   tokens = (const int*)  d_in[0];   // [B,S]
    const float* emb    = (const float*)d_in[1];   // [V,E]
    const float* w_ih0  = (const float*)d_in[2];   // [2,4H,E]  -> flat [1024,300]
    const float* w_hh0  = (const float*)d_in[3];   // [2,4H,H]
    const float* b0     = (const float*)d_in[4];   // [2,4H]    -> flat [1024]
    const float* w_ih1  = (const float*)d_in[5];   // [2,4H,2H] -> flat [1024,256]
    const float* w_hh1  = (const float*)d_in[6];   // [2,4H,H]
    const float* b1     = (const float*)d_in[7];   // [2,4H]
    const float* fc1w   = (const float*)d_in[8];   // [H,2H]
    const float* fc1b   = (const float*)d_in[9];   // [H]
    const float* fc2w   = (const float*)d_in[10];  // [2,H]
    const float* fc2b   = (const float*)d_in[11];  // [2]
    float* out = (float*)d_out;

    static int configured = 0;
    if (!configured) {
        cudaFuncSetAttribute((const void*)recur_kernel<0>,
                             cudaFuncAttributeMaxDynamicSharedMemorySize, REC_SMEM_BYTES);
        cudaFuncSetAttribute((const void*)recur_kernel<1>,
                             cudaFuncAttributeMaxDynamicSharedMemorySize, REC_SMEM_BYTES);
        configured = 1;
    }

    // 1) Projected vocab table: P = emb @ w_ih0^T + b0   [50000,1024]
    {
        dim3 grid(NG / 128, (VV + 127) / 128);   // (8, 391)
        gemm_bias_kernel<0><<<grid, 256>>>(emb, w_ih0, b0, VV, EE);
    }
    // 2) Layer-0 bidirectional recurrence (gx gathered from P)
    {
        dim3 grid(64, 2);
        recur_kernel<0><<<grid, 512, REC_SMEM_BYTES>>>(tokens, w_hh0);
    }
    // 3) Layer-1 input projections: gx1 = h0_seq @ w_ih1^T + b1  [131072,1024]
    {
        dim3 grid(NG / 128, (SS * BB) / 128);    // (8, 1024)
        gemm_bias_kernel<1><<<grid, 256>>>(nullptr, w_ih1, b1, SS * BB, 256);
    }
    // 4) Layer-1 bidirectional recurrence -> final hidden states
    {
        dim3 grid(64, 2);
        recur_kernel<1><<<grid, 512, REC_SMEM_BYTES>>>(tokens, w_hh1);
    }
    // 5) MLP head
    fc_kernel<<<BB, 128>>>(fc1w, fc1b, fc2w, fc2b, out);
}

// round 8
// speedup vs baseline: 1.3092x; 1.2991x over previous
#include <cuda_runtime.h>
#include <cuda_bf16.h>
#include <cstdint>
#include <cstddef>

// Problem constants
#define BB   256     // batch
#define SS   512     // seq len
#define VV   50000   // vocab
#define EE   300     // embed dim
#define HH   128     // hidden
#define NG   1024    // 2 dirs * 4H gate columns

// ---------------------------------------------------------------------------
// Scratch (static device globals — no runtime allocation allowed)
// ---------------------------------------------------------------------------
__device__ __align__(16) float g_P  [(size_t)VV * NG];        // projected vocab table (+b0 folded)
__device__ __align__(16) float g_h0 [(size_t)SS * BB * 256];  // layer-0 output [s*B+b][2H]
__device__ __align__(16) float g_gx1[(size_t)SS * BB * NG];   // layer-1 input projections (+b1 folded)
__device__ __align__(16) float g_hT [(size_t)BB * 256];       // layer-1 final hidden [b][2H]

// ---------------------------------------------------------------------------
// Helpers
// ---------------------------------------------------------------------------
__device__ __forceinline__ uint32_t smem_u32(const void* p) {
    uint32_t a;
    asm("{ .reg .u64 t; cvta.to.shared.u64 t, %1; cvt.u32.u64 %0, t; }"
        : "=r"(a) : "l"(p));
    return a;
}
__device__ __forceinline__ void ffma2(unsigned long long& c,
                                      unsigned long long a,
                                      unsigned long long b) {
    asm("fma.rn.f32x2 %0, %1, %2, %0;" : "+l"(c) : "l"(a), "l"(b));
}
__device__ __forceinline__ float2 unpk2(unsigned long long v) {
    float2 f;
    asm("mov.b64 {%0, %1}, %2;" : "=f"(f.x), "=f"(f.y) : "l"(v));
    return f;
}
__device__ __forceinline__ float sigm_f(float x) {
    return 1.0f / (1.0f + __expf(-x));
}
__device__ __forceinline__ float tanh_f(float x) {
    float a = fabsf(x);
    float t = __expf(-2.0f * a);
    float r = (1.0f - t) / (1.0f + t);
    return copysignf(r, x);
}

// ldmatrix x4 (b16) — baseline PTX (sm_75+), legal on compute_103
__device__ __forceinline__ void ldm4(uint32_t& r0, uint32_t& r1,
                                     uint32_t& r2, uint32_t& r3, uint32_t addr) {
    asm volatile("ldmatrix.sync.aligned.m8n8.x4.shared.b16 {%0,%1,%2,%3}, [%4];"
                 : "=r"(r0), "=r"(r1), "=r"(r2), "=r"(r3) : "r"(addr));
}
// mma m16n8k16 bf16 -> f32 accumulate — baseline PTX (sm_80+)
__device__ __forceinline__ void mma16816(float* d, const uint32_t* a,
                                         uint32_t b0, uint32_t b1) {
    asm volatile(
        "mma.sync.aligned.m16n8k16.row.col.f32.bf16.bf16.f32 "
        "{%0,%1,%2,%3}, {%4,%5,%6,%7}, {%8,%9}, {%0,%1,%2,%3};"
        : "+f"(d[0]), "+f"(d[1]), "+f"(d[2]), "+f"(d[3])
        : "r"(a[0]), "r"(a[1]), "r"(a[2]), "r"(a[3]), "r"(b0), "r"(b1));
}

// ---------------------------------------------------------------------------
// Tensor-core GEMM via mma.sync, split-bf16 fp32 emulation:
//   C[M,1024] = A[M,K] @ Bw[1024,K]^T + bias   (acc += AhBh + AhBl + AlBh)
// BM=128, BN=128, BK=32, 256 threads = 8 warps (4 m x 2 n), warp tile 32x64.
// Smem: bf16 hi/lo tiles, pitch 40 bf16 (80B) -> conflict-free ldmatrix.
// WHICH==0: A=Aarg(emb), C=g_P.  WHICH==1: A=g_h0, C=g_gx1.
// ---------------------------------------------------------------------------
#define GP 40   // smem pitch in bf16 elements

template<int WHICH>
__global__ __launch_bounds__(256, 2)
void gemm_mma(const float* __restrict__ Aarg, const float* __restrict__ Bw,
              const float* __restrict__ bias, int M, int K)
{
    __shared__ __align__(16) __nv_bfloat16 Ahs[128 * GP];
    __shared__ __align__(16) __nv_bfloat16 Als[128 * GP];
    __shared__ __align__(16) __nv_bfloat16 Bhs[128 * GP];
    __shared__ __align__(16) __nv_bfloat16 Bls[128 * GP];

    const float* __restrict__ A = (WHICH == 0) ? Aarg : g_h0;
    float* __restrict__ C       = (WHICH == 0) ? g_P  : g_gx1;

    const int tid  = threadIdx.x;
    const int wid  = tid >> 5;
    const int lane = tid & 31;
    const int wm   = wid & 3;    // m warp 0..3 (32 rows each)
    const int wn   = wid >> 2;   // n warp 0..1 (64 cols each)

    const int mTile = blockIdx.y * 128;
    const int nTile = blockIdx.x * 128;

    const uint32_t uAh = smem_u32(Ahs), uAl = smem_u32(Als);
    const uint32_t uBh = smem_u32(Bhs), uBl = smem_u32(Bls);

    // ldmatrix lane-address geometry (derived per m16n8k16 fragment layouts)
    const int a_row = ((lane >> 3) & 1) * 8 + (lane & 7);
    const int a_k   = (lane >> 4) * 8;
    const int b_row = (lane >> 4) * 8 + (lane & 7);
    const int b_k   = ((lane >> 3) & 1) * 8;

    float acc[2][8][4];
    #pragma unroll
    for (int i = 0; i < 2; i++)
        #pragma unroll
        for (int j = 0; j < 8; j++)
            #pragma unroll
            for (int q = 0; q < 4; q++) acc[i][j][q] = 0.0f;

    // fill geometry: thread -> (row = tid>>1, 4 float4 at qbase=(tid&1)*4)
    const int frow  = tid >> 1;
    const int qbase = (tid & 1) * 4;
    const int nKT = (K + 31) >> 5;

    for (int kt = 0; kt < nKT; kt++) {
        const int k0 = kt << 5;

        // ---- fill A hi/lo (row mTile+frow) and B hi/lo (row nTile+frow)
        #pragma unroll
        for (int i = 0; i < 4; i++) {
            const int q  = qbase + i;
            const int gk = k0 + q * 4;
            const int gm = mTile + frow;
            float4 va = make_float4(0.f, 0.f, 0.f, 0.f);
            if (gm < M && gk + 3 < K)
                va = *reinterpret_cast<const float4*>(&A[(size_t)gm * K + gk]);
            float4 vb = make_float4(0.f, 0.f, 0.f, 0.f);
            if (gk + 3 < K)
                vb = *reinterpret_cast<const float4*>(&Bw[(size_t)(nTile + frow) * K + gk]);

            __nv_bfloat16 ahx = __float2bfloat16(va.x), ahy = __float2bfloat16(va.y);
            __nv_bfloat16 ahz = __float2bfloat16(va.z), ahw = __float2bfloat16(va.w);
            __nv_bfloat16 alx = __float2bfloat16(va.x - __bfloat162float(ahx));
            __nv_bfloat16 aly = __float2bfloat16(va.y - __bfloat162float(ahy));
            __nv_bfloat16 alz = __float2bfloat16(va.z - __bfloat162float(ahz));
            __nv_bfloat16 alw = __float2bfloat16(va.w - __bfloat162float(ahw));
            __nv_bfloat16 bhx = __float2bfloat16(vb.x), bhy = __float2bfloat16(vb.y);
            __nv_bfloat16 bhz = __float2bfloat16(vb.z), bhw = __float2bfloat16(vb.w);
            __nv_bfloat16 blx = __float2bfloat16(vb.x - __bfloat162float(bhx));
            __nv_bfloat16 bly = __float2bfloat16(vb.y - __bfloat162float(bhy));
            __nv_bfloat16 blz = __float2bfloat16(vb.z - __bfloat162float(bhz));
            __nv_bfloat16 blw = __float2bfloat16(vb.w - __bfloat162float(bhw));

            union { __nv_bfloat162 h[2]; uint2 u; } t;
            const int so = frow * GP + q * 4;
            t.h[0] = __halves2bfloat162(ahx, ahy); t.h[1] = __halves2bfloat162(ahz, ahw);
            *reinterpret_cast<uint2*>(&Ahs[so]) = t.u;
            t.h[0] = __halves2bfloat162(alx, aly); t.h[1] = __halves2bfloat162(alz, alw);
            *reinterpret_cast<uint2*>(&Als[so]) = t.u;
            t.h[0] = __halves2bfloat162(bhx, bhy); t.h[1] = __halves2bfloat162(bhz, bhw);
            *reinterpret_cast<uint2*>(&Bhs[so]) = t.u;
            t.h[0] = __halves2bfloat162(blx, bly); t.h[1] = __halves2bfloat162(blz, blw);
            *reinterpret_cast<uint2*>(&Bls[so]) = t.u;
        }
        __syncthreads();

        // ---- 2 k16 steps per chunk
        #pragma unroll
        for (int ks = 0; ks < 2; ks++) {
            uint32_t ah[2][4], al[2][4];
            #pragma unroll
            for (int mt = 0; mt < 2; mt++) {
                const uint32_t off =
                    (uint32_t)(((wm * 32 + mt * 16 + a_row) * GP + ks * 16 + a_k) * 2);
                ldm4(ah[mt][0], ah[mt][1], ah[mt][2], ah[mt][3], uAh + off);
                ldm4(al[mt][0], al[mt][1], al[mt][2], al[mt][3], uAl + off);
            }
            #pragma unroll
            for (int np = 0; np < 4; np++) {   // 2 n8-tiles per ldmatrix.x4
                const uint32_t off =
                    (uint32_t)(((wn * 64 + np * 16 + b_row) * GP + ks * 16 + b_k) * 2);
                uint32_t bh[4], bl[4];
                ldm4(bh[0], bh[1], bh[2], bh[3], uBh + off);
                ldm4(bl[0], bl[1], bl[2], bl[3], uBl + off);
                #pragma unroll
                for (int h2 = 0; h2 < 2; h2++) {
                    #pragma unroll
                    for (int mt = 0; mt < 2; mt++) {
                        float* d = acc[mt][np * 2 + h2];
                        mma16816(d, ah[mt], bh[2 * h2], bh[2 * h2 + 1]);
                        mma16816(d, ah[mt], bl[2 * h2], bl[2 * h2 + 1]);
                        mma16816(d, al[mt], bh[2 * h2], bh[2 * h2 + 1]);
                    }
                }
            }
        }
        __syncthreads();
    }

    // ---- epilogue: c-frag lane mapping rows lane>>2 (+8), cols (lane&3)*2
    const int lrow = lane >> 2;
    const int lcol = (lane & 3) * 2;
    #pragma unroll
    for (int mt = 0; mt < 2; mt++) {
        const int gm0 = mTile + wm * 32 + mt * 16 + lrow;
        #pragma unroll
        for (int nt = 0; nt < 8; nt++) {
            const int gn0 = nTile + wn * 64 + nt * 8 + lcol;
            const float bz0 = bias[gn0], bz1 = bias[gn0 + 1];
            if (gm0 < M) {
                float2 v = make_float2(acc[mt][nt][0] + bz0, acc[mt][nt][1] + bz1);
                *reinterpret_cast<float2*>(&C[(size_t)gm0 * NG + gn0]) = v;
            }
            if (gm0 + 8 < M) {
                float2 v = make_float2(acc[mt][nt][2] + bz0, acc[mt][nt][3] + bz1);
                *reinterpret_cast<float2*>(&C[(size_t)(gm0 + 8) * NG + gn0]) = v;
            }
        }
    }
}

// ---------------------------------------------------------------------------
// Recurrence kernel (unchanged — known passing). One block = 4 batch rows x
// one direction. Thread t owns gate row g=t; w k[0,64) in regs, k[64,128) in
// smem quad-transposed; f32x2 k-pair accumulation.
// ---------------------------------------------------------------------------
#define REC_SMEM_BYTES ((32768 + 512 + 2560) * 4 + 2048 * 4)

template<int LAYER>
__global__ __launch_bounds__(512, 1)
void recur_kernel(const int* __restrict__ tokens,
                  const float* __restrict__ w_hh)   // [2,512,128]
{
    extern __shared__ __align__(16) float smem[];
    float* w_sm4  = smem;                    // [16][512][4] floats
    float* h_sm   = smem + 32768;            // [4][128]
    float* z_sm   = h_sm + 512;              // [512][5]
    int*   tok_sm = (int*)(z_sm + 2560);     // [4][512]

    const int tid   = threadIdx.x;
    const int chunk = blockIdx.x;
    const int dir   = blockIdx.y;
    const int g     = tid;

    unsigned long long wr2[32];
    {
        const unsigned long long* wp = reinterpret_cast<const unsigned long long*>(
            &w_hh[((size_t)dir * 512 + g) * 128]);
        #pragma unroll
        for (int i = 0; i < 32; i++) wr2[i] = wp[i];
    }
    for (int idx = tid; idx < 512 * 64; idx += 512) {
        int gg = idx >> 6, kk = idx & 63;
        w_sm4[(kk >> 2) * 2048 + gg * 4 + (kk & 3)] =
            w_hh[((size_t)dir * 512 + gg) * 128 + 64 + kk];
    }
    if (LAYER == 0) {
        for (int idx = tid; idx < 4 * 512; idx += 512)
            tok_sm[idx] = tokens[(size_t)(chunk * 4 + (idx >> 9)) * SS + (idx & 511)];
    }
    h_sm[tid] = 0.0f;
    __syncthreads();

    const int jj = tid & 127;
    const int bb = tid >> 7;
    const int col = dir * 512 + g;
    const float* __restrict__ gsrc = (LAYER == 0) ? g_P : g_gx1;
    float c_st = 0.0f, h_last = 0.0f;

    for (int si = 0; si < 512; si++) {
        const int s = dir ? (511 - si) : si;

        float gxv[4];
        #pragma unroll
        for (int b = 0; b < 4; b++) {
            size_t row = (LAYER == 0)
                ? (size_t)tok_sm[b * 512 + s]
                : ((size_t)s * BB + (chunk * 4 + b));
            gxv[b] = gsrc[row * NG + col];
        }

        unsigned long long acc[4] = {0ull, 0ull, 0ull, 0ull};
        #pragma unroll
        for (int t = 0; t < 16; t++) {
            #pragma unroll
            for (int b = 0; b < 4; b++) {
                ulonglong2 h2 = *reinterpret_cast<const ulonglong2*>(&h_sm[b * 128 + t * 4]);
                ffma2(acc[b], wr2[2 * t],     h2.x);
                ffma2(acc[b], wr2[2 * t + 1], h2.y);
            }
        }
        #pragma unroll
        for (int t = 0; t < 16; t++) {
            ulonglong2 w2 = *reinterpret_cast<const ulonglong2*>(&w_sm4[t * 2048 + g * 4]);
            #pragma unroll
            for (int b = 0; b < 4; b++) {
                ulonglong2 h2 = *reinterpret_cast<const ulonglong2*>(&h_sm[b * 128 + 64 + t * 4]);
                ffma2(acc[b], w2.x, h2.x);
                ffma2(acc[b], w2.y, h2.y);
            }
        }
        #pragma unroll
        for (int b = 0; b < 4; b++) {
            float2 f = unpk2(acc[b]);
            z_sm[g * 5 + b] = f.x + f.y + gxv[b];
        }
        __syncthreads();

        {
            float zi = z_sm[(      jj) * 5 + bb];
            float zf = z_sm[(128 + jj) * 5 + bb];
            float zg = z_sm[(256 + jj) * 5 + bb];
            float zo = z_sm[(384 + jj) * 5 + bb];
            float ig = sigm_f(zi), fg = sigm_f(zf), og = sigm_f(zo);
            float gv = tanh_f(zg);
            c_st = fg * c_st + ig * gv;
            float hh = og * tanh_f(c_st);
            h_last = hh;
            h_sm[bb * 128 + jj] = hh;
            if (LAYER == 0)
                g_h0[((size_t)s * BB + (chunk * 4 + bb)) * 256 + dir * 128 + jj] = hh;
        }
        __syncthreads();
    }

    if (LAYER == 1)
        g_hT[(size_t)(chunk * 4 + bb) * 256 + dir * 128 + jj] = h_last;
}

// ---------------------------------------------------------------------------
// FC head
// ---------------------------------------------------------------------------
__global__ __launch_bounds__(128)
void fc_kernel(const float* __restrict__ fc1w, const float* __restrict__ fc1b,
               const float* __restrict__ fc2w, const float* __restrict__ fc2b,
               float* __restrict__ out)
{
    __shared__ float xs[256];
    __shared__ float red[4];
    const int b = blockIdx.x, tid = threadIdx.x;
    xs[tid]       = g_hT[(size_t)b * 256 + tid];
    xs[tid + 128] = g_hT[(size_t)b * 256 + 128 + tid];
    __syncthreads();

    float s = fc1b[tid];
    const float* wr = &fc1w[(size_t)tid * 256];
    #pragma unroll 8
    for (int k = 0; k < 256; k++) s += xs[k] * wr[k];
    float a = fmaxf(s, 0.0f);

    for (int o = 0; o < 2; o++) {
        float v = a * fc2w[o * 128 + tid];
        #pragma unroll
        for (int off = 16; off > 0; off >>= 1)
            v += __shfl_xor_sync(0xffffffffu, v, off);
        if ((tid & 31) == 0) red[tid >> 5] = v;
        __syncthreads();
        if (tid == 0)
            out[b * 2 + o] = red[0] + red[1] + red[2] + red[3] + fc2b[o];
        __syncthreads();
    }
}

// ---------------------------------------------------------------------------
// Launcher (graph-capturable: kernel launches only, default stream)
// ---------------------------------------------------------------------------
extern "C" void kernel_launch(void* const* d_in, const int* in_sizes, int n_in,
                              void* d_out, int out_size)
{
    const int*   tokens = (const int*)  d_in[0];
    const float* emb    = (const float*)d_in[1];
    const float* w_ih0  = (const float*)d_in[2];   // flat [1024,300]
    const float* w_hh0  = (const float*)d_in[3];
    const float* b0     = (const float*)d_in[4];   // flat [1024]
    const float* w_ih1  = (const float*)d_in[5];   // flat [1024,256]
    const float* w_hh1  = (const float*)d_in[6];
    const float* b1     = (const float*)d_in[7];
    const float* fc1w   = (const float*)d_in[8];
    const float* fc1b   = (const float*)d_in[9];
    const float* fc2w   = (const float*)d_in[10];
    const float* fc2b   = (const float*)d_in[11];
    float* out = (float*)d_out;

    static int configured = 0;
    if (!configured) {
        cudaFuncSetAttribute((const void*)recur_kernel<0>,
                             cudaFuncAttributeMaxDynamicSharedMemorySize, REC_SMEM_BYTES);
        cudaFuncSetAttribute((const void*)recur_kernel<1>,
                             cudaFuncAttributeMaxDynamicSharedMemorySize, REC_SMEM_BYTES);
        configured = 1;
    }

    // 1) Projected vocab table: P = emb @ w_ih0^T + b0   [50000,1024]
    {
        dim3 grid(NG / 128, (VV + 127) / 128);   // (8, 391)
        gemm_mma<0><<<grid, 256>>>(emb, w_ih0, b0, VV, EE);
    }
    // 2) Layer-0 bidirectional recurrence (gx gathered from P)
    {
        dim3 grid(64, 2);
        recur_kernel<0><<<grid, 512, REC_SMEM_BYTES>>>(tokens, w_hh0);
    }
    // 3) Layer-1 input projections: gx1 = h0_seq @ w_ih1^T + b1  [131072,1024]
    {
        dim3 grid(NG / 128, (SS * BB) / 128);    // (8, 1024)
        gemm_mma<1><<<grid, 256>>>(nullptr, w_ih1, b1, SS * BB, 256);
    }
    // 4) Layer-1 bidirectional recurrence -> final hidden states
    {
        dim3 grid(64, 2);
        recur_kernel<1><<<grid, 512, REC_SMEM_BYTES>>>(tokens, w_hh1);
    }
    // 5) MLP head
    fc_kernel<<<BB, 128>>>(fc1w, fc1b, fc2w, fc2b, out);
}

// round 9
// speedup vs baseline: 1.6169x; 1.2350x over previous
#include <cuda_runtime.h>
#include <cuda_bf16.h>
#include <cstdint>
#include <cstddef>

// Problem constants
#define BB   256     // batch
#define SS   512     // seq len
#define VV   50000   // vocab
#define EE   300     // embed dim
#define HH   128     // hidden
#define NG   1024    // 2 dirs * 4H gate columns

// ---------------------------------------------------------------------------
// Scratch (static device globals — no runtime allocation allowed)
// ---------------------------------------------------------------------------
__device__ __align__(16) float g_P  [(size_t)VV * NG];        // projected vocab table (+b0 folded)
__device__ __align__(16) float g_h0 [(size_t)SS * BB * 256];  // layer-0 output [s*B+b][2H]
__device__ __align__(16) float g_gx1[(size_t)SS * BB * NG];   // layer-1 input projections (+b1 folded)
__device__ __align__(16) float g_hT [(size_t)BB * 256];       // layer-1 final hidden [b][2H]

// ---------------------------------------------------------------------------
// Helpers
// ---------------------------------------------------------------------------
__device__ __forceinline__ uint32_t smem_u32(const void* p) {
    uint32_t a;
    asm("{ .reg .u64 t; cvta.to.shared.u64 t, %1; cvt.u32.u64 %0, t; }"
        : "=r"(a) : "l"(p));
    return a;
}
__device__ __forceinline__ void ffma2(unsigned long long& c,
                                      unsigned long long a,
                                      unsigned long long b) {
    asm("fma.rn.f32x2 %0, %1, %2, %0;" : "+l"(c) : "l"(a), "l"(b));
}
__device__ __forceinline__ float2 unpk2(unsigned long long v) {
    float2 f;
    asm("mov.b64 {%0, %1}, %2;" : "=f"(f.x), "=f"(f.y) : "l"(v));
    return f;
}
__device__ __forceinline__ float sigm_f(float x) {
    return 1.0f / (1.0f + __expf(-x));
}
__device__ __forceinline__ float tanh_f(float x) {
    float a = fabsf(x);
    float t = __expf(-2.0f * a);
    float r = (1.0f - t) / (1.0f + t);
    return copysignf(r, x);
}

// ldmatrix x4 (b16) — baseline PTX (sm_75+), legal on compute_103
__device__ __forceinline__ void ldm4(uint32_t& r0, uint32_t& r1,
                                     uint32_t& r2, uint32_t& r3, uint32_t addr) {
    asm volatile("ldmatrix.sync.aligned.m8n8.x4.shared.b16 {%0,%1,%2,%3}, [%4];"
                 : "=r"(r0), "=r"(r1), "=r"(r2), "=r"(r3) : "r"(addr));
}
// mma m16n8k16 bf16 -> f32 accumulate — baseline PTX (sm_80+)
__device__ __forceinline__ void mma16816(float* d, const uint32_t* a,
                                         uint32_t b0, uint32_t b1) {
    asm volatile(
        "mma.sync.aligned.m16n8k16.row.col.f32.bf16.bf16.f32 "
        "{%0,%1,%2,%3}, {%4,%5,%6,%7}, {%8,%9}, {%0,%1,%2,%3};"
        : "+f"(d[0]), "+f"(d[1]), "+f"(d[2]), "+f"(d[3])
        : "r"(a[0]), "r"(a[1]), "r"(a[2]), "r"(a[3]), "r"(b0), "r"(b1));
}

// ---------------------------------------------------------------------------
// Tensor-core GEMM via mma.sync, split-bf16 fp32 emulation (UNCHANGED — R8 win)
//   C[M,1024] = A[M,K] @ Bw[1024,K]^T + bias   (acc += AhBh + AhBl + AlBh)
// ---------------------------------------------------------------------------
#define GP 40   // smem pitch in bf16 elements

template<int WHICH>
__global__ __launch_bounds__(256, 2)
void gemm_mma(const float* __restrict__ Aarg, const float* __restrict__ Bw,
              const float* __restrict__ bias, int M, int K)
{
    __shared__ __align__(16) __nv_bfloat16 Ahs[128 * GP];
    __shared__ __align__(16) __nv_bfloat16 Als[128 * GP];
    __shared__ __align__(16) __nv_bfloat16 Bhs[128 * GP];
    __shared__ __align__(16) __nv_bfloat16 Bls[128 * GP];

    const float* __restrict__ A = (WHICH == 0) ? Aarg : g_h0;
    float* __restrict__ C       = (WHICH == 0) ? g_P  : g_gx1;

    const int tid  = threadIdx.x;
    const int wid  = tid >> 5;
    const int lane = tid & 31;
    const int wm   = wid & 3;
    const int wn   = wid >> 2;

    const int mTile = blockIdx.y * 128;
    const int nTile = blockIdx.x * 128;

    const uint32_t uAh = smem_u32(Ahs), uAl = smem_u32(Als);
    const uint32_t uBh = smem_u32(Bhs), uBl = smem_u32(Bls);

    const int a_row = ((lane >> 3) & 1) * 8 + (lane & 7);
    const int a_k   = (lane >> 4) * 8;
    const int b_row = (lane >> 4) * 8 + (lane & 7);
    const int b_k   = ((lane >> 3) & 1) * 8;

    float acc[2][8][4];
    #pragma unroll
    for (int i = 0; i < 2; i++)
        #pragma unroll
        for (int j = 0; j < 8; j++)
            #pragma unroll
            for (int q = 0; q < 4; q++) acc[i][j][q] = 0.0f;

    const int frow  = tid >> 1;
    const int qbase = (tid & 1) * 4;
    const int nKT = (K + 31) >> 5;

    for (int kt = 0; kt < nKT; kt++) {
        const int k0 = kt << 5;

        #pragma unroll
        for (int i = 0; i < 4; i++) {
            const int q  = qbase + i;
            const int gk = k0 + q * 4;
            const int gm = mTile + frow;
            float4 va = make_float4(0.f, 0.f, 0.f, 0.f);
            if (gm < M && gk + 3 < K)
                va = *reinterpret_cast<const float4*>(&A[(size_t)gm * K + gk]);
            float4 vb = make_float4(0.f, 0.f, 0.f, 0.f);
            if (gk + 3 < K)
                vb = *reinterpret_cast<const float4*>(&Bw[(size_t)(nTile + frow) * K + gk]);

            __nv_bfloat16 ahx = __float2bfloat16(va.x), ahy = __float2bfloat16(va.y);
            __nv_bfloat16 ahz = __float2bfloat16(va.z), ahw = __float2bfloat16(va.w);
            __nv_bfloat16 alx = __float2bfloat16(va.x - __bfloat162float(ahx));
            __nv_bfloat16 aly = __float2bfloat16(va.y - __bfloat162float(ahy));
            __nv_bfloat16 alz = __float2bfloat16(va.z - __bfloat162float(ahz));
            __nv_bfloat16 alw = __float2bfloat16(va.w - __bfloat162float(ahw));
            __nv_bfloat16 bhx = __float2bfloat16(vb.x), bhy = __float2bfloat16(vb.y);
            __nv_bfloat16 bhz = __float2bfloat16(vb.z), bhw = __float2bfloat16(vb.w);
            __nv_bfloat16 blx = __float2bfloat16(vb.x - __bfloat162float(bhx));
            __nv_bfloat16 bly = __float2bfloat16(vb.y - __bfloat162float(bhy));
            __nv_bfloat16 blz = __float2bfloat16(vb.z - __bfloat162float(bhz));
            __nv_bfloat16 blw = __float2bfloat16(vb.w - __bfloat162float(bhw));

            union { __nv_bfloat162 h[2]; uint2 u; } t;
            const int so = frow * GP + q * 4;
            t.h[0] = __halves2bfloat162(ahx, ahy); t.h[1] = __halves2bfloat162(ahz, ahw);
            *reinterpret_cast<uint2*>(&Ahs[so]) = t.u;
            t.h[0] = __halves2bfloat162(alx, aly); t.h[1] = __halves2bfloat162(alz, alw);
            *reinterpret_cast<uint2*>(&Als[so]) = t.u;
            t.h[0] = __halves2bfloat162(bhx, bhy); t.h[1] = __halves2bfloat162(bhz, bhw);
            *reinterpret_cast<uint2*>(&Bhs[so]) = t.u;
            t.h[0] = __halves2bfloat162(blx, bly); t.h[1] = __halves2bfloat162(blz, blw);
            *reinterpret_cast<uint2*>(&Bls[so]) = t.u;
        }
        __syncthreads();

        #pragma unroll
        for (int ks = 0; ks < 2; ks++) {
            uint32_t ah[2][4], al[2][4];
            #pragma unroll
            for (int mt = 0; mt < 2; mt++) {
                const uint32_t off =
                    (uint32_t)(((wm * 32 + mt * 16 + a_row) * GP + ks * 16 + a_k) * 2);
                ldm4(ah[mt][0], ah[mt][1], ah[mt][2], ah[mt][3], uAh + off);
                ldm4(al[mt][0], al[mt][1], al[mt][2], al[mt][3], uAl + off);
            }
            #pragma unroll
            for (int np = 0; np < 4; np++) {
                const uint32_t off =
                    (uint32_t)(((wn * 64 + np * 16 + b_row) * GP + ks * 16 + b_k) * 2);
                uint32_t bh[4], bl[4];
                ldm4(bh[0], bh[1], bh[2], bh[3], uBh + off);
                ldm4(bl[0], bl[1], bl[2], bl[3], uBl + off);
                #pragma unroll
                for (int h2 = 0; h2 < 2; h2++) {
                    #pragma unroll
                    for (int mt = 0; mt < 2; mt++) {
                        float* d = acc[mt][np * 2 + h2];
                        mma16816(d, ah[mt], bh[2 * h2], bh[2 * h2 + 1]);
                        mma16816(d, ah[mt], bl[2 * h2], bl[2 * h2 + 1]);
                        mma16816(d, al[mt], bh[2 * h2], bh[2 * h2 + 1]);
                    }
                }
            }
        }
        __syncthreads();
    }

    const int lrow = lane >> 2;
    const int lcol = (lane & 3) * 2;
    #pragma unroll
    for (int mt = 0; mt < 2; mt++) {
        const int gm0 = mTile + wm * 32 + mt * 16 + lrow;
        #pragma unroll
        for (int nt = 0; nt < 8; nt++) {
            const int gn0 = nTile + wn * 64 + nt * 8 + lcol;
            const float bz0 = bias[gn0], bz1 = bias[gn0 + 1];
            if (gm0 < M) {
                float2 v = make_float2(acc[mt][nt][0] + bz0, acc[mt][nt][1] + bz1);
                *reinterpret_cast<float2*>(&C[(size_t)gm0 * NG + gn0]) = v;
            }
            if (gm0 + 8 < M) {
                float2 v = make_float2(acc[mt][nt][2] + bz0, acc[mt][nt][3] + bz1);
                *reinterpret_cast<float2*>(&C[(size_t)(gm0 + 8) * NG + gn0]) = v;
            }
        }
    }
}

// ---------------------------------------------------------------------------
// Recurrence v2: G=2 gates per thread, k-split 2 — halves h broadcast
// wavefronts (the measured bottleneck: L1 72.6%).
// Thread t: gp = t>>1 (gate pair), kh = t&1 (k-half [kh*64, kh*64+64)).
//   gate g0 = 2*gp   : w half-row in 32 u64 REGISTERS
//   gate g1 = 2*gp+1 : w half-row in smem, slot layout [warp][t][lane][4] so a
//                      warp's LDS.128 are 32 consecutive 16B (minimal 4 wf).
// h_sm has 72-float half-pitch so the warp's 2-address (kh) loads are 1 wf.
// Partial z reduced across kh pairs with ONE shfl_xor(1) per (gate,b):
// each thread sends its OTHER-gate partial — the partner needs exactly that.
// Thread t writes z for gate (2*gp+kh) == t, so gx col = dir*512 + t (as before).
// Combiner (cell bb=t>>7, jj=t&127) unchanged, c-state in register.
// smem (floats): w_sm 32768 | h_sm 576 | z_sm 2560 | tok 2048 ints
// ---------------------------------------------------------------------------
#define REC_SMEM_BYTES ((32768 + 576 + 2560) * 4 + 2048 * 4)

template<int LAYER>
__global__ __launch_bounds__(512, 1)
void recur_kernel(const int* __restrict__ tokens,
                  const float* __restrict__ w_hh)   // [2,512,128]
{
    extern __shared__ __align__(16) float smem[];
    float* w_sm   = smem;                    // [16 warps][16 t][32 lanes][4]
    float* h_sm   = smem + 32768;            // [4 b][2 kh x 72]
    float* z_sm   = h_sm + 576;              // [512][5]
    int*   tok_sm = (int*)(z_sm + 2560);     // [4][512]

    const int tid   = threadIdx.x;
    const int chunk = blockIdx.x;
    const int dir   = blockIdx.y;
    const int gp    = tid >> 1;
    const int kh    = tid & 1;
    const int warp  = tid >> 5;
    const int lane  = tid & 31;

    // ---- w for gate g0 = 2*gp, k-half kh: 32 packed k-pairs in registers
    unsigned long long wr2[32];
    {
        const unsigned long long* wp = reinterpret_cast<const unsigned long long*>(
            &w_hh[((size_t)dir * 512 + 2 * gp) * 128 + kh * 64]);
        #pragma unroll
        for (int i = 0; i < 32; i++) wr2[i] = wp[i];
    }
    // ---- w for gate g1 = 2*gp+1, k-half kh: into own smem slots
    {
        const float* wsrc = &w_hh[((size_t)dir * 512 + 2 * gp + 1) * 128 + kh * 64];
        float* wdst = &w_sm[(size_t)(warp * 16 * 32 + lane) * 4];
        #pragma unroll
        for (int t = 0; t < 16; t++)
            *reinterpret_cast<float4*>(&wdst[t * 128]) =
                *reinterpret_cast<const float4*>(&wsrc[t * 4]);
    }
    if (LAYER == 0) {
        for (int idx = tid; idx < 4 * 512; idx += 512)
            tok_sm[idx] = tokens[(size_t)(chunk * 4 + (idx >> 9)) * SS + (idx & 511)];
    }
    for (int idx = tid; idx < 576; idx += 512) h_sm[idx] = 0.0f;
    __syncthreads();

    const int jj = tid & 127;
    const int bb = tid >> 7;
    const int col = dir * 512 + tid;   // z row this thread writes = gate tid
    const float* __restrict__ gsrc = (LAYER == 0) ? g_P : g_gx1;
    const float* wslot = &w_sm[(size_t)(warp * 16 * 32 + lane) * 4];
    float c_st = 0.0f, h_last = 0.0f;

    for (int si = 0; si < 512; si++) {
        const int s = dir ? (511 - si) : si;

        // --- input projection for this thread's z gate (latency hidden by dot)
        float gxv[4];
        #pragma unroll
        for (int b = 0; b < 4; b++) {
            size_t row = (LAYER == 0)
                ? (size_t)tok_sm[b * 512 + s]
                : ((size_t)s * BB + (chunk * 4 + b));
            gxv[b] = gsrc[row * NG + col];
        }

        // --- dot over this thread's k-half for gates g0 (regs) and g1 (smem)
        unsigned long long accA[4] = {0ull, 0ull, 0ull, 0ull};  // g0
        unsigned long long accB[4] = {0ull, 0ull, 0ull, 0ull};  // g1
        #pragma unroll
        for (int t = 0; t < 16; t++) {
            ulonglong2 w2 = *reinterpret_cast<const ulonglong2*>(&wslot[t * 128]);
            #pragma unroll
            for (int b = 0; b < 4; b++) {
                ulonglong2 h2 = *reinterpret_cast<const ulonglong2*>(
                    &h_sm[b * 144 + kh * 72 + t * 4]);
                ffma2(accA[b], wr2[2 * t],     h2.x);
                ffma2(accA[b], wr2[2 * t + 1], h2.y);
                ffma2(accB[b], w2.x, h2.x);
                ffma2(accB[b], w2.y, h2.y);
            }
        }
        // --- reduce: intra-pair add, then exchange other-gate partial with
        //     the kh-partner (shfl_xor 1).  z[gate tid] = own + partner + gx.
        #pragma unroll
        for (int b = 0; b < 4; b++) {
            float2 fA = unpk2(accA[b]);
            float2 fB = unpk2(accB[b]);
            float sA = fA.x + fA.y;            // partial for g0
            float sB = fB.x + fB.y;            // partial for g1
            float send = kh ? sA : sB;          // partner's write-gate partial
            float recv = __shfl_xor_sync(0xffffffffu, send, 1);
            float own  = kh ? sB : sA;          // my write-gate partial
            z_sm[tid * 5 + b] = own + recv + gxv[b];
        }
        __syncthreads();

        // --- gate combine (torch order i,f,g,o) for cell (bb, jj)
        {
            float zi = z_sm[(      jj) * 5 + bb];
            float zf = z_sm[(128 + jj) * 5 + bb];
            float zg = z_sm[(256 + jj) * 5 + bb];
            float zo = z_sm[(384 + jj) * 5 + bb];
            float ig = sigm_f(zi), fg = sigm_f(zf), og = sigm_f(zo);
            float gv = tanh_f(zg);
            c_st = fg * c_st + ig * gv;
            float hh = og * tanh_f(c_st);
            h_last = hh;
            h_sm[bb * 144 + (jj >> 6) * 72 + (jj & 63)] = hh;
            if (LAYER == 0)
                g_h0[((size_t)s * BB + (chunk * 4 + bb)) * 256 + dir * 128 + jj] = hh;
        }
        __syncthreads();
    }

    if (LAYER == 1)
        g_hT[(size_t)(chunk * 4 + bb) * 256 + dir * 128 + jj] = h_last;
}

// ---------------------------------------------------------------------------
// FC head
// ---------------------------------------------------------------------------
__global__ __launch_bounds__(128)
void fc_kernel(const float* __restrict__ fc1w, const float* __restrict__ fc1b,
               const float* __restrict__ fc2w, const float* __restrict__ fc2b,
               float* __restrict__ out)
{
    __shared__ float xs[256];
    __shared__ float red[4];
    const int b = blockIdx.x, tid = threadIdx.x;
    xs[tid]       = g_hT[(size_t)b * 256 + tid];
    xs[tid + 128] = g_hT[(size_t)b * 256 + 128 + tid];
    __syncthreads();

    float s = fc1b[tid];
    const float* wr = &fc1w[(size_t)tid * 256];
    #pragma unroll 8
    for (int k = 0; k < 256; k++) s += xs[k] * wr[k];
    float a = fmaxf(s, 0.0f);

    for (int o = 0; o < 2; o++) {
        float v = a * fc2w[o * 128 + tid];
        #pragma unroll
        for (int off = 16; off > 0; off >>= 1)
            v += __shfl_xor_sync(0xffffffffu, v, off);
        if ((tid & 31) == 0) red[tid >> 5] = v;
        __syncthreads();
        if (tid == 0)
            out[b * 2 + o] = red[0] + red[1] + red[2] + red[3] + fc2b[o];
        __syncthreads();
    }
}

// ---------------------------------------------------------------------------
// Launcher (graph-capturable: kernel launches only, default stream)
// ---------------------------------------------------------------------------
extern "C" void kernel_launch(void* const* d_in, const int* in_sizes, int n_in,
                              void* d_out, int out_size)
{
    const int*   tokens = (const int*)  d_in[0];
    const float* emb    = (const float*)d_in[1];
    const float* w_ih0  = (const float*)d_in[2];   // flat [1024,300]
    const float* w_hh0  = (const float*)d_in[3];
    const float* b0     = (const float*)d_in[4];   // flat [1024]
    const float* w_ih1  = (const float*)d_in[5];   // flat [1024,256]
    const float* w_hh1  = (const float*)d_in[6];
    const float* b1     = (const float*)d_in[7];
    const float* fc1w   = (const float*)d_in[8];
    const float* fc1b   = (const float*)d_in[9];
    const float* fc2w   = (const float*)d_in[10];
    const float* fc2b   = (const float*)d_in[11];
    float* out = (float*)d_out;

    static int configured = 0;
    if (!configured) {
        cudaFuncSetAttribute((const void*)recur_kernel<0>,
                             cudaFuncAttributeMaxDynamicSharedMemorySize, REC_SMEM_BYTES);
        cudaFuncSetAttribute((const void*)recur_kernel<1>,
                             cudaFuncAttributeMaxDynamicSharedMemorySize, REC_SMEM_BYTES);
        configured = 1;
    }

    // 1) Projected vocab table: P = emb @ w_ih0^T + b0   [50000,1024]
    {
        dim3 grid(NG / 128, (VV + 127) / 128);   // (8, 391)
        gemm_mma<0><<<grid, 256>>>(emb, w_ih0, b0, VV, EE);
    }
    // 2) Layer-0 bidirectional recurrence (gx gathered from P)
    {
        dim3 grid(64, 2);
        recur_kernel<0><<<grid, 512, REC_SMEM_BYTES>>>(tokens, w_hh0);
    }
    // 3) Layer-1 input projections: gx1 = h0_seq @ w_ih1^T + b1  [131072,1024]
    {
        dim3 grid(NG / 128, (SS * BB) / 128);    // (8, 1024)
        gemm_mma<1><<<grid, 256>>>(nullptr, w_ih1, b1, SS * BB, 256);
    }
    // 4) Layer-1 bidirectional recurrence -> final hidden states
    {
        dim3 grid(64, 2);
        recur_kernel<1><<<grid, 512, REC_SMEM_BYTES>>>(tokens, w_hh1);
    }
    // 5) MLP head
    fc_kernel<<<BB, 128>>>(fc1w, fc1b, fc2w, fc2b, out);
}